// round 1
// baseline (speedup 1.0000x reference)
#include <cuda_runtime.h>
#include <cstdint>
#include <math.h>

#define BB   8
#define NN   4096
#define HID  64
#define JJ   128
#define CAP  96
#define NROWS (BB*NN)   // 32768

// ---- scratch (device globals; no allocation allowed) ----
__device__ int   g_cnt[NROWS];
__device__ int   g_idx[(size_t)NROWS * CAP];   // packed: col | (val==2 ? 0x80000000 : 0)
__device__ float g_h1[(size_t)NROWS * HID];    // 8 MB
__device__ float g_h2[(size_t)NROWS * HID];    // 8 MB
__device__ float g_gge[BB * HID];              // global graph embedding accumulator

// ============================================================================
// Kernel 1: stream adj once. Per row: pooled0 (2 feats) + sparse list + GIN0 MLP.
// 8 rows per block, 256 threads.
// ============================================================================
__global__ __launch_bounds__(256) void k1_scan(
    const float* __restrict__ adj, const float* __restrict__ feat,
    const float* __restrict__ w1, const float* __restrict__ b1,
    const float* __restrict__ w2, const float* __restrict__ b2)
{
    __shared__ float s_w2[HID * HID];   // 16 KB
    __shared__ float s_w1[2 * HID];
    __shared__ float s_b1[HID], s_b2[HID];
    __shared__ float s_p[8][2];
    __shared__ int   s_cnt[8];
    __shared__ float s_z[8][HID];

    const int tid = threadIdx.x;

    for (int i = tid; i < HID * HID; i += 256) s_w2[i] = w2[i];
    if (tid < 2 * HID) s_w1[tid] = w1[tid];
    if (tid < HID) { s_b1[tid] = b1[tid]; s_b2[tid] = b2[tid]; }
    if (tid < 8) { s_cnt[tid] = 0; s_p[tid][0] = 0.f; s_p[tid][1] = 0.f; }
    if (blockIdx.x == 0)   // zero the pooling accumulator before kernel 2 runs
        for (int i = tid; i < BB * HID; i += 256) g_gge[i] = 0.f;
    __syncthreads();

    const int row0 = blockIdx.x * 8;

    // Phase A: scan 8 adjacency rows (no syncs between rows)
    for (int rr = 0; rr < 8; rr++) {
        const int r = row0 + rr;
        const int b = r >> 12;                       // r / 4096
        const float4* arow = (const float4*)(adj + (size_t)r * NN);
        const float2* f2p  = (const float2*)feat + (size_t)b * NN;
        float p0 = 0.f, p1 = 0.f;
        bool any = false;
        #pragma unroll
        for (int k = 0; k < 4; k++) {
            const int i4 = tid + k * 256;
            const float4 v = arow[i4];
            const int jbase = i4 * 4;
            #pragma unroll
            for (int l = 0; l < 4; l++) {
                const float val = (l == 0) ? v.x : (l == 1) ? v.y : (l == 2) ? v.z : v.w;
                if (val != 0.0f) {
                    const int j = jbase + l;
                    const int pos = atomicAdd(&s_cnt[rr], 1);
                    if (pos < CAP)
                        g_idx[(size_t)r * CAP + pos] = j | ((val > 1.5f) ? 0x80000000 : 0);
                    const float2 f = f2p[j];
                    p0 += val * f.x; p1 += val * f.y;
                    any = true;
                }
            }
        }
        if (any) { atomicAdd(&s_p[rr][0], p0); atomicAdd(&s_p[rr][1], p1); }
    }
    __syncthreads();

    if (tid < 8) g_cnt[row0 + tid] = min(s_cnt[tid], CAP);

    // Phase B: GIN0 MLP for the 8 nodes (2 -> 64 -> 64, relu both)
    const int h = tid & 63;
    for (int rr = tid >> 6; rr < 8; rr += 4) {
        float z = s_b1[h] + s_p[rr][0] * s_w1[h] + s_p[rr][1] * s_w1[HID + h];
        s_z[rr][h] = fmaxf(z, 0.f);
    }
    __syncthreads();
    for (int rr = tid >> 6; rr < 8; rr += 4) {
        float acc = s_b2[h];
        #pragma unroll
        for (int k = 0; k < HID; k++) acc += s_z[rr][k] * s_w2[k * HID + h];
        g_h1[(size_t)(row0 + rr) * HID + h] = fmaxf(acc, 0.f);
    }
}

// ============================================================================
// Kernel 2: sparse SpMM (layer 1) + GIN1 MLP + fused graph pooling.
// 16 nodes per block, 256 threads (4 slots x 64 features).
// ============================================================================
__global__ __launch_bounds__(256) void k2_spmm(
    const float* __restrict__ w1, const float* __restrict__ b1,
    const float* __restrict__ w2, const float* __restrict__ b2,
    const float* __restrict__ gp)
{
    __shared__ float s_w1[HID * HID];   // 16 KB
    __shared__ float s_w2[HID * HID];   // 16 KB
    __shared__ float s_b1[HID], s_b2[HID];
    __shared__ float s_pool[16][HID];
    __shared__ float s_z[16][HID];
    __shared__ float s_acc[HID];

    const int tid = threadIdx.x;
    for (int i = tid; i < HID * HID; i += 256) { s_w1[i] = w1[i]; s_w2[i] = w2[i]; }
    if (tid < HID) { s_b1[tid] = b1[tid]; s_b2[tid] = b2[tid]; s_acc[tid] = 0.f; }
    __syncthreads();

    const int h = tid & 63, slot = tid >> 6;
    const int base = blockIdx.x * 16;
    const int b = base >> 12;            // all 16 nodes in one batch (16 | 4096)
    const size_t bbase = (size_t)(b << 12);

    // Phase A: gather pooled1 from sparse lists
    for (int q = 0; q < 4; q++) {
        const int ln = slot * 4 + q;
        const int r = base + ln;
        const int cnt = g_cnt[r];
        const int* ip = g_idx + (size_t)r * CAP;
        float acc = 0.f;
        for (int k = 0; k < cnt; k++) {
            const int enc = ip[k];
            const int j = enc & 0x7fffffff;
            const float v = (enc < 0) ? 2.f : 1.f;
            acc += v * g_h1[(bbase + j) * HID + h];
        }
        s_pool[ln][h] = acc;
    }
    __syncthreads();

    // Phase B: z = relu(pool @ w1 + b1)
    for (int q = 0; q < 4; q++) {
        const int ln = slot * 4 + q;
        float z = s_b1[h];
        #pragma unroll
        for (int f = 0; f < HID; f++) z += s_pool[ln][f] * s_w1[f * HID + h];
        s_z[ln][h] = fmaxf(z, 0.f);
    }
    __syncthreads();

    // Phase C: h2 = relu(z @ w2 + b2), plus pooling contribution
    float gacc = 0.f;
    for (int q = 0; q < 4; q++) {
        const int ln = slot * 4 + q;
        const int r = base + ln;
        float acc = s_b2[h];
        #pragma unroll
        for (int k = 0; k < HID; k++) acc += s_z[ln][k] * s_w2[k * HID + h];
        acc = fmaxf(acc, 0.f);
        g_h2[(size_t)r * HID + h] = acc;
        gacc += gp[r] * acc;
    }
    atomicAdd(&s_acc[h], gacc);
    __syncthreads();
    if (slot == 0) atomicAdd(&g_gge[b * HID + h], s_acc[h]);
}

// ============================================================================
// Kernel 3: candidate gather + actor MLP (192->64 tanh ->64 tanh ->1) + softmax.
// One block per batch, 128 threads (one per candidate job).
// ============================================================================
__global__ __launch_bounds__(JJ) void k3_actor(
    const int* __restrict__ cand, const int* __restrict__ mask,
    const float* __restrict__ pmi,
    const float* __restrict__ w1, const float* __restrict__ b1,
    const float* __restrict__ w2, const float* __restrict__ b2,
    const float* __restrict__ w3, const float* __restrict__ b3,
    float* __restrict__ out)
{
    __shared__ float s_g[HID], s_pmi[HID];
    __shared__ float s_t[JJ][HID + 1];   // padded: conflict-free column reads
    __shared__ float s_red[JJ];

    const int b = blockIdx.x, j = threadIdx.x;
    if (j < HID) { s_g[j] = g_gge[b * HID + j]; s_pmi[j] = pmi[j]; }
    __syncthreads();

    const int c = cand[b * JJ + j];
    const float* emb = g_h2 + ((size_t)b * NN + c) * HID;

    float a[HID];
    #pragma unroll
    for (int h = 0; h < HID; h++) a[h] = b1[h];
    for (int f = 0; f < HID; f++) {
        const float x = emb[f];
        const float* w = w1 + f * HID;
        #pragma unroll
        for (int h = 0; h < HID; h++) a[h] += x * w[h];
    }
    for (int f = 0; f < HID; f++) {
        const float x = s_g[f];
        const float* w = w1 + (HID + f) * HID;
        #pragma unroll
        for (int h = 0; h < HID; h++) a[h] += x * w[h];
    }
    for (int f = 0; f < HID; f++) {
        const float x = s_pmi[f];
        const float* w = w1 + (2 * HID + f) * HID;
        #pragma unroll
        for (int h = 0; h < HID; h++) a[h] += x * w[h];
    }
    #pragma unroll
    for (int h = 0; h < HID; h++) s_t[j][h] = tanhf(a[h]);

    #pragma unroll
    for (int h = 0; h < HID; h++) a[h] = b2[h];
    for (int k = 0; k < HID; k++) {
        const float x = s_t[j][k];
        const float* w = w2 + k * HID;
        #pragma unroll
        for (int h = 0; h < HID; h++) a[h] += x * w[h];
    }

    float score = b3[0];
    #pragma unroll
    for (int h = 0; h < HID; h++) score += tanhf(a[h]) * w3[h];
    score *= 10.0f;
    if (mask[b * JJ + j]) score = -INFINITY;

    // masked softmax over the 128 jobs
    const float sc = score;
    s_red[j] = sc; __syncthreads();
    for (int s = JJ / 2; s > 0; s >>= 1) {
        if (j < s) s_red[j] = fmaxf(s_red[j], s_red[j + s]);
        __syncthreads();
    }
    const float mx = s_red[0]; __syncthreads();
    const float e = expf(sc - mx);
    s_red[j] = e; __syncthreads();
    for (int s = JJ / 2; s > 0; s >>= 1) {
        if (j < s) s_red[j] += s_red[j + s];
        __syncthreads();
    }
    out[b * JJ + j] = e / s_red[0];
}

// ============================================================================
extern "C" void kernel_launch(void* const* d_in, const int* in_sizes, int n_in,
                              void* d_out, int out_size)
{
    const float* features   = (const float*)d_in[0];
    const float* graph_pool = (const float*)d_in[1];
    const float* adj        = (const float*)d_in[2];
    const int*   candidate  = (const int*)d_in[3];
    const int*   mask       = (const int*)d_in[4];
    const float* g0w1 = (const float*)d_in[5];
    const float* g0b1 = (const float*)d_in[6];
    const float* g0w2 = (const float*)d_in[7];
    const float* g0b2 = (const float*)d_in[8];
    const float* g1w1 = (const float*)d_in[9];
    const float* g1b1 = (const float*)d_in[10];
    const float* g1w2 = (const float*)d_in[11];
    const float* g1b2 = (const float*)d_in[12];
    const float* pmi  = (const float*)d_in[13];
    const float* aw1  = (const float*)d_in[14];
    const float* ab1  = (const float*)d_in[15];
    const float* aw2  = (const float*)d_in[16];
    const float* ab2  = (const float*)d_in[17];
    const float* aw3  = (const float*)d_in[18];
    const float* ab3  = (const float*)d_in[19];
    float* out = (float*)d_out;

    k1_scan<<<NROWS / 8, 256>>>(adj, features, g0w1, g0b1, g0w2, g0b2);
    k2_spmm<<<NROWS / 16, 256>>>(g1w1, g1b1, g1w2, g1b2, graph_pool);
    k3_actor<<<BB, JJ>>>(candidate, mask, pmi, aw1, ab1, aw2, ab2, aw3, ab3, out);
}

// round 2
// speedup vs baseline: 3.0648x; 3.0648x over previous
#include <cuda_runtime.h>
#include <cstdint>
#include <math.h>

#define BB   8
#define NN   4096
#define HID  64
#define JJ   128
#define CAP  96
#define NROWS (BB*NN)   // 32768

// ---- scratch (device globals; no allocation allowed) ----
__device__ int   g_cnt[NROWS];
__device__ int   g_idx[(size_t)NROWS * CAP];   // packed: col | (val==2 ? 0x80000000 : 0)
__device__ float g_h1[(size_t)NROWS * HID];    // 8 MB
__device__ float g_h2[(size_t)NROWS * HID];    // 8 MB
__device__ float g_gge[BB * HID];              // global graph embedding accumulator
__device__ float g_scores[BB * JJ];            // actor scores before softmax

// ============================================================================
// Kernel 1: stream adj once. Warp-per-row: ballot-compacted sparse list +
// pooled features + fused GIN0 MLP (2->64->64). 16 rows / 512-thread block.
// ============================================================================
__global__ __launch_bounds__(512) void k1_scan(
    const float* __restrict__ adj, const float* __restrict__ feat,
    const float* __restrict__ w1, const float* __restrict__ b1,
    const float* __restrict__ w2, const float* __restrict__ b2)
{
    __shared__ float s_w2[HID * HID];   // 16 KB
    __shared__ float s_w1[2 * HID];
    __shared__ float s_b1[HID], s_b2[HID];
    __shared__ float s_p[16][2];
    __shared__ float s_z[16][HID];

    const int tid  = threadIdx.x;
    const int w    = tid >> 5;          // warp 0..15
    const int lane = tid & 31;

    for (int i = tid; i < HID * HID; i += 512) s_w2[i] = w2[i];
    if (tid < 2 * HID) s_w1[tid] = w1[tid];
    if (tid < HID) { s_b1[tid] = b1[tid]; s_b2[tid] = b2[tid]; }
    if (blockIdx.x == 0) {              // zero pooling accumulator for k2
        if (tid < BB * HID) g_gge[tid] = 0.f;
    }

    // ---- Phase A: each warp scans one full adjacency row ----
    const int r = blockIdx.x * 16 + w;
    const int b = r >> 12;
    const float4* arow4 = (const float4*)(adj + (size_t)r * NN);   // 1024 float4
    const float2* f2p   = (const float2*)feat + (size_t)b * NN;
    int* __restrict__ irow = g_idx + (size_t)r * CAP;

    float p0 = 0.f, p1 = 0.f;
    int base = 0;

    #pragma unroll 1
    for (int chunk = 0; chunk < 8; chunk++) {
        float4 v[4];
        #pragma unroll
        for (int k = 0; k < 4; k++)
            v[k] = arow4[chunk * 128 + lane + 32 * k];
        #pragma unroll
        for (int k = 0; k < 4; k++) {
            const int jb = (chunk * 128 + lane + 32 * k) * 4;
            #pragma unroll
            for (int c = 0; c < 4; c++) {
                const float val = (c == 0) ? v[k].x : (c == 1) ? v[k].y
                                : (c == 2) ? v[k].z : v[k].w;
                const bool nz = (val != 0.0f);
                const unsigned m = __ballot_sync(0xffffffffu, nz);
                if (nz) {
                    const int j = jb + c;
                    const int off = base + __popc(m & ((1u << lane) - 1u));
                    const bool two = (val > 1.5f);
                    if (off < CAP)
                        irow[off] = j | (two ? 0x80000000 : 0);
                    const float2 f = f2p[j];
                    const float s = two ? 2.f : 1.f;
                    p0 += s * f.x; p1 += s * f.y;
                }
                base += __popc(m);
            }
        }
    }
    // warp-reduce pooled features
    #pragma unroll
    for (int o = 16; o > 0; o >>= 1) {
        p0 += __shfl_down_sync(0xffffffffu, p0, o);
        p1 += __shfl_down_sync(0xffffffffu, p1, o);
    }
    if (lane == 0) {
        s_p[w][0] = p0; s_p[w][1] = p1;
        g_cnt[r] = min(base, CAP);
    }
    __syncthreads();

    // ---- Phase B: GIN0 MLP for 16 rows (2 -> 64 relu -> 64 relu) ----
    const int h = tid & 63;
    const int slot = tid >> 6;          // 0..7
    #pragma unroll
    for (int t = 0; t < 2; t++) {
        const int rr = slot + t * 8;
        const float z = s_b1[h] + s_p[rr][0] * s_w1[h] + s_p[rr][1] * s_w1[HID + h];
        s_z[rr][h] = fmaxf(z, 0.f);
    }
    __syncthreads();
    #pragma unroll
    for (int t = 0; t < 2; t++) {
        const int rr = slot + t * 8;
        float acc = s_b2[h];
        #pragma unroll
        for (int k = 0; k < HID; k++) acc += s_z[rr][k] * s_w2[k * HID + h];
        g_h1[(size_t)(blockIdx.x * 16 + rr) * HID + h] = fmaxf(acc, 0.f);
    }
}

// ============================================================================
// Kernel 2: sparse SpMM (layer 1, 4-way unrolled gather) + GIN1 MLP +
// fused graph pooling. 16 nodes per block, 256 threads.
// ============================================================================
__global__ __launch_bounds__(256) void k2_spmm(
    const float* __restrict__ w1, const float* __restrict__ b1,
    const float* __restrict__ w2, const float* __restrict__ b2,
    const float* __restrict__ gp)
{
    __shared__ float s_w1[HID * HID];   // 16 KB
    __shared__ float s_w2[HID * HID];   // 16 KB
    __shared__ float s_b1[HID], s_b2[HID];
    __shared__ float s_pool[16][HID];
    __shared__ float s_z[16][HID];
    __shared__ float s_acc[HID];

    const int tid = threadIdx.x;
    for (int i = tid; i < HID * HID; i += 256) { s_w1[i] = w1[i]; s_w2[i] = w2[i]; }
    if (tid < HID) { s_b1[tid] = b1[tid]; s_b2[tid] = b2[tid]; s_acc[tid] = 0.f; }
    __syncthreads();

    const int h = tid & 63, slot = tid >> 6;
    const int base = blockIdx.x * 16;
    const int b = base >> 12;
    const float* __restrict__ h1b = g_h1 + ((size_t)(b << 12)) * HID;

    // Phase A: gather pooled1 from sparse lists, 4 neighbors in flight
    #pragma unroll
    for (int q = 0; q < 4; q++) {
        const int ln = slot * 4 + q;
        const int r = base + ln;
        const int cnt = g_cnt[r];
        const int* __restrict__ ip = g_idx + (size_t)r * CAP;
        float a0 = 0.f, a1 = 0.f, a2 = 0.f, a3 = 0.f;
        int k = 0;
        for (; k + 4 <= cnt; k += 4) {
            const int4 e = *(const int4*)(ip + k);
            const float f0 = h1b[(size_t)(e.x & 0x7fffffff) * HID + h];
            const float f1 = h1b[(size_t)(e.y & 0x7fffffff) * HID + h];
            const float f2 = h1b[(size_t)(e.z & 0x7fffffff) * HID + h];
            const float f3 = h1b[(size_t)(e.w & 0x7fffffff) * HID + h];
            a0 += (e.x < 0) ? 2.f * f0 : f0;
            a1 += (e.y < 0) ? 2.f * f1 : f1;
            a2 += (e.z < 0) ? 2.f * f2 : f2;
            a3 += (e.w < 0) ? 2.f * f3 : f3;
        }
        for (; k < cnt; k++) {
            const int enc = ip[k];
            const float f = h1b[(size_t)(enc & 0x7fffffff) * HID + h];
            a0 += (enc < 0) ? 2.f * f : f;
        }
        s_pool[ln][h] = (a0 + a1) + (a2 + a3);
    }
    __syncthreads();

    // Phase B: z = relu(pool @ w1 + b1)
    #pragma unroll
    for (int q = 0; q < 4; q++) {
        const int ln = slot * 4 + q;
        float z = s_b1[h];
        #pragma unroll
        for (int f = 0; f < HID; f++) z += s_pool[ln][f] * s_w1[f * HID + h];
        s_z[ln][h] = fmaxf(z, 0.f);
    }
    __syncthreads();

    // Phase C: h2 = relu(z @ w2 + b2) + pooling contribution
    float gacc = 0.f;
    #pragma unroll
    for (int q = 0; q < 4; q++) {
        const int ln = slot * 4 + q;
        const int r = base + ln;
        float acc = s_b2[h];
        #pragma unroll
        for (int k = 0; k < HID; k++) acc += s_z[ln][k] * s_w2[k * HID + h];
        acc = fmaxf(acc, 0.f);
        g_h2[(size_t)r * HID + h] = acc;
        gacc += gp[r] * acc;
    }
    atomicAdd(&s_acc[h], gacc);
    __syncthreads();
    if (slot == 0) atomicAdd(&g_gge[b * HID + h], s_acc[h]);
}

// ============================================================================
// Kernel 3a: actor MLP, one warp per (batch, job). 256 blocks x 128 threads.
// Each lane owns 2 hidden units (h = lane, lane+32). Weights hit L1.
// ============================================================================
__global__ __launch_bounds__(128) void k3a_actor(
    const int* __restrict__ cand, const int* __restrict__ mask,
    const float* __restrict__ pmi,
    const float* __restrict__ w1, const float* __restrict__ b1,
    const float* __restrict__ w2, const float* __restrict__ b2,
    const float* __restrict__ w3, const float* __restrict__ b3)
{
    __shared__ float s_x[4][3 * HID];
    __shared__ float s_t[4][HID];

    const int w    = threadIdx.x >> 5;
    const int lane = threadIdx.x & 31;
    const int job  = blockIdx.x * 4 + w;      // 0..1023
    const int b    = job >> 7;
    const int j    = job & 127;

    // assemble x = [job_emb | global_emb | pmi]  (192 floats)
    const int c = cand[b * JJ + j];
    const float2* e2 = (const float2*)(g_h2 + ((size_t)b * NN + c) * HID);
    const float2* g2 = (const float2*)(g_gge + b * HID);
    const float2* p2 = (const float2*)pmi;
    float2 t;
    t = e2[lane]; s_x[w][2 * lane] = t.x; s_x[w][2 * lane + 1] = t.y;
    t = g2[lane]; s_x[w][HID + 2 * lane] = t.x; s_x[w][HID + 2 * lane + 1] = t.y;
    t = p2[lane]; s_x[w][2 * HID + 2 * lane] = t.x; s_x[w][2 * HID + 2 * lane + 1] = t.y;
    __syncwarp();

    // layer 1: 192 -> 64, tanh
    float a0 = b1[lane], a1 = b1[lane + 32];
    #pragma unroll 8
    for (int f = 0; f < 3 * HID; f++) {
        const float xv = s_x[w][f];
        a0 += xv * w1[f * HID + lane];
        a1 += xv * w1[f * HID + lane + 32];
    }
    s_t[w][lane] = tanhf(a0); s_t[w][lane + 32] = tanhf(a1);
    __syncwarp();

    // layer 2: 64 -> 64, tanh
    float c0 = b2[lane], c1 = b2[lane + 32];
    #pragma unroll 8
    for (int k = 0; k < HID; k++) {
        const float xv = s_t[w][k];
        c0 += xv * w2[k * HID + lane];
        c1 += xv * w2[k * HID + lane + 32];
    }

    // layer 3: 64 -> 1
    float part = tanhf(c0) * w3[lane] + tanhf(c1) * w3[lane + 32];
    #pragma unroll
    for (int o = 16; o > 0; o >>= 1)
        part += __shfl_down_sync(0xffffffffu, part, o);
    if (lane == 0) {
        float score = (part + b3[0]) * 10.0f;
        if (mask[b * JJ + j]) score = -INFINITY;
        g_scores[job] = score;
    }
}

// ============================================================================
// Kernel 3b: masked softmax over jobs, one block per batch.
// ============================================================================
__global__ __launch_bounds__(JJ) void k3b_softmax(float* __restrict__ out)
{
    __shared__ float s_red[JJ];
    const int b = blockIdx.x, j = threadIdx.x;
    const float sc = g_scores[b * JJ + j];
    s_red[j] = sc; __syncthreads();
    for (int s = JJ / 2; s > 0; s >>= 1) {
        if (j < s) s_red[j] = fmaxf(s_red[j], s_red[j + s]);
        __syncthreads();
    }
    const float mx = s_red[0]; __syncthreads();
    const float e = expf(sc - mx);
    s_red[j] = e; __syncthreads();
    for (int s = JJ / 2; s > 0; s >>= 1) {
        if (j < s) s_red[j] += s_red[j + s];
        __syncthreads();
    }
    out[b * JJ + j] = e / s_red[0];
}

// ============================================================================
extern "C" void kernel_launch(void* const* d_in, const int* in_sizes, int n_in,
                              void* d_out, int out_size)
{
    const float* features   = (const float*)d_in[0];
    const float* graph_pool = (const float*)d_in[1];
    const float* adj        = (const float*)d_in[2];
    const int*   candidate  = (const int*)d_in[3];
    const int*   mask       = (const int*)d_in[4];
    const float* g0w1 = (const float*)d_in[5];
    const float* g0b1 = (const float*)d_in[6];
    const float* g0w2 = (const float*)d_in[7];
    const float* g0b2 = (const float*)d_in[8];
    const float* g1w1 = (const float*)d_in[9];
    const float* g1b1 = (const float*)d_in[10];
    const float* g1w2 = (const float*)d_in[11];
    const float* g1b2 = (const float*)d_in[12];
    const float* pmi  = (const float*)d_in[13];
    const float* aw1  = (const float*)d_in[14];
    const float* ab1  = (const float*)d_in[15];
    const float* aw2  = (const float*)d_in[16];
    const float* ab2  = (const float*)d_in[17];
    const float* aw3  = (const float*)d_in[18];
    const float* ab3  = (const float*)d_in[19];
    float* out = (float*)d_out;

    k1_scan<<<NROWS / 16, 512>>>(adj, features, g0w1, g0b1, g0w2, g0b2);
    k2_spmm<<<NROWS / 16, 256>>>(g1w1, g1b1, g1w2, g1b2, graph_pool);
    k3a_actor<<<BB * JJ / 4, 128>>>(candidate, mask, pmi,
                                    aw1, ab1, aw2, ab2, aw3, ab3);
    k3b_softmax<<<BB, JJ>>>(out);
}

// round 3
// speedup vs baseline: 3.0923x; 1.0090x over previous
#include <cuda_runtime.h>
#include <cstdint>
#include <math.h>

#define BB   8
#define NN   4096
#define HID  64
#define JJ   128
#define CAP  96
#define NROWS (BB*NN)   // 32768
#define NTILES (NROWS/16)

// ---- scratch (device globals; no allocation allowed) ----
__device__ int   g_cnt[NROWS];
__device__ int   g_idx[(size_t)NROWS * CAP];   // packed: col | (val==2 ? 0x80000000 : 0)
__device__ float g_h1[(size_t)NROWS * HID];    // 8 MB
__device__ float g_h2[(size_t)NROWS * HID];    // 8 MB
__device__ float g_gge[BB * HID];              // global graph embedding accumulator
__device__ float g_scores[BB * JJ];            // actor scores before softmax
__device__ int   g_done[BB];                   // per-batch completion counters

// ============================================================================
// Kernel 1: stream adj once. Warp-per-row, group-skip nonzero detection
// (1 ballot per 4 elements; compaction only on nonzero groups) + pooled
// features + fused GIN0 MLP (2->64->64). 16 rows / 512-thread block.
// ============================================================================
__global__ __launch_bounds__(512) void k1_scan(
    const float* __restrict__ adj, const float* __restrict__ feat,
    const float* __restrict__ w1, const float* __restrict__ b1,
    const float* __restrict__ w2, const float* __restrict__ b2)
{
    __shared__ float s_w2[HID * HID];   // 16 KB
    __shared__ float s_w1[2 * HID];
    __shared__ float s_b1[HID], s_b2[HID];
    __shared__ float s_p[16][2];
    __shared__ float s_z[16][HID];

    const int tid  = threadIdx.x;
    const int w    = tid >> 5;
    const int lane = tid & 31;
    const unsigned lmask = (1u << lane) - 1u;

    for (int i = tid; i < HID * HID; i += 512) s_w2[i] = w2[i];
    if (tid < 2 * HID) s_w1[tid] = w1[tid];
    if (tid < HID) { s_b1[tid] = b1[tid]; s_b2[tid] = b2[tid]; }
    if (blockIdx.x == 0) {              // zero accumulators for k2/k3
        if (tid < BB * HID) g_gge[tid] = 0.f;
        if (tid < BB) g_done[tid] = 0;
    }

    // ---- Phase A: each warp scans one full adjacency row ----
    const int r = blockIdx.x * 16 + w;
    const int b = r >> 12;
    const uint4* __restrict__ arow = (const uint4*)(adj + (size_t)r * NN);  // 1024
    const float2* __restrict__ f2p = (const float2*)feat + (size_t)b * NN;
    int* __restrict__ irow = g_idx + (size_t)r * CAP;

    float p0 = 0.f, p1 = 0.f;
    int base = 0;

#define PROC_ELEM(bits, jj) do {                                           \
        const bool nz = (bits) != 0u;                                      \
        const unsigned m = __ballot_sync(0xffffffffu, nz);                 \
        if (nz) {                                                          \
            const int off = base + __popc(m & lmask);                      \
            const bool two = ((bits) == 0x40000000u);                      \
            if (off < CAP) irow[off] = (jj) | (two ? 0x80000000 : 0);      \
            const float2 f = f2p[(jj)];                                    \
            const float sv = two ? 2.f : 1.f;                              \
            p0 += sv * f.x; p1 += sv * f.y;                                \
        }                                                                  \
        base += __popc(m);                                                 \
    } while (0)

    #pragma unroll 1
    for (int it = 0; it < 8; it++) {
        uint4 v0 = arow[it * 128 + lane];
        uint4 v1 = arow[it * 128 + lane + 32];
        uint4 v2 = arow[it * 128 + lane + 64];
        uint4 v3 = arow[it * 128 + lane + 96];
        #pragma unroll
        for (int k = 0; k < 4; k++) {
            const uint4 v = (k == 0) ? v0 : (k == 1) ? v1 : (k == 2) ? v2 : v3;
            const unsigned any = v.x | v.y | v.z | v.w;
            const unsigned grp = __ballot_sync(0xffffffffu, any != 0u);
            if (grp) {   // warp-uniform: rare (~4% of groups)
                const int jb = (it * 128 + lane + 32 * k) * 4;
                PROC_ELEM(v.x, jb + 0);
                PROC_ELEM(v.y, jb + 1);
                PROC_ELEM(v.z, jb + 2);
                PROC_ELEM(v.w, jb + 3);
            }
        }
    }
#undef PROC_ELEM

    // warp-reduce pooled features
    #pragma unroll
    for (int o = 16; o > 0; o >>= 1) {
        p0 += __shfl_down_sync(0xffffffffu, p0, o);
        p1 += __shfl_down_sync(0xffffffffu, p1, o);
    }
    if (lane == 0) {
        s_p[w][0] = p0; s_p[w][1] = p1;
        g_cnt[r] = min(base, CAP);
    }
    __syncthreads();

    // ---- Phase B: GIN0 MLP for 16 rows (2 -> 64 relu -> 64 relu) ----
    const int h = tid & 63;
    const int slot = tid >> 6;          // 0..7
    #pragma unroll
    for (int t = 0; t < 2; t++) {
        const int rr = slot + t * 8;
        const float z = s_b1[h] + s_p[rr][0] * s_w1[h] + s_p[rr][1] * s_w1[HID + h];
        s_z[rr][h] = fmaxf(z, 0.f);
    }
    __syncthreads();
    #pragma unroll
    for (int t = 0; t < 2; t++) {
        const int rr = slot + t * 8;
        float acc = s_b2[h];
        #pragma unroll
        for (int k = 0; k < HID; k++) acc += s_z[rr][k] * s_w2[k * HID + h];
        g_h1[(size_t)(blockIdx.x * 16 + rr) * HID + h] = fmaxf(acc, 0.f);
    }
}

// ============================================================================
// Kernel 2: persistent blocks, grid-stride over 16-node tiles. Sparse SpMM
// (layer 1) + GIN1 MLP + fused graph pooling. Weights loaded once per block.
// ============================================================================
__global__ __launch_bounds__(256) void k2_spmm(
    const float* __restrict__ w1, const float* __restrict__ b1,
    const float* __restrict__ w2, const float* __restrict__ b2,
    const float* __restrict__ gp)
{
    __shared__ float s_w1[HID * HID];   // 16 KB
    __shared__ float s_w2[HID * HID];   // 16 KB
    __shared__ float s_b1[HID], s_b2[HID];
    __shared__ float s_pool[16][HID];
    __shared__ float s_z[16][HID];
    __shared__ float s_acc[HID];

    const int tid = threadIdx.x;
    for (int i = tid; i < HID * HID; i += 256) { s_w1[i] = w1[i]; s_w2[i] = w2[i]; }
    if (tid < HID) { s_b1[tid] = b1[tid]; s_b2[tid] = b2[tid]; s_acc[tid] = 0.f; }

    const int h = tid & 63, slot = tid >> 6;

    #pragma unroll 1
    for (int tile = blockIdx.x; tile < NTILES; tile += gridDim.x) {
        const int base = tile * 16;
        const int b = base >> 8 >> 4;    // base / 4096
        const float* __restrict__ h1b = g_h1 + ((size_t)(b << 12)) * HID;
        __syncthreads();   // protects s_pool/s_z reuse + s_acc reset visibility

        // Phase A: gather pooled1 from sparse lists, 4 neighbors in flight
        #pragma unroll
        for (int q = 0; q < 4; q++) {
            const int ln = slot * 4 + q;
            const int r = base + ln;
            const int cnt = g_cnt[r];
            const int* __restrict__ ip = g_idx + (size_t)r * CAP;
            float a0 = 0.f, a1 = 0.f, a2 = 0.f, a3 = 0.f;
            int k = 0;
            for (; k + 4 <= cnt; k += 4) {
                const int4 e = *(const int4*)(ip + k);
                const float f0 = h1b[(size_t)(e.x & 0x7fffffff) * HID + h];
                const float f1 = h1b[(size_t)(e.y & 0x7fffffff) * HID + h];
                const float f2 = h1b[(size_t)(e.z & 0x7fffffff) * HID + h];
                const float f3 = h1b[(size_t)(e.w & 0x7fffffff) * HID + h];
                a0 += (e.x < 0) ? 2.f * f0 : f0;
                a1 += (e.y < 0) ? 2.f * f1 : f1;
                a2 += (e.z < 0) ? 2.f * f2 : f2;
                a3 += (e.w < 0) ? 2.f * f3 : f3;
            }
            for (; k < cnt; k++) {
                const int enc = ip[k];
                const float f = h1b[(size_t)(enc & 0x7fffffff) * HID + h];
                a0 += (enc < 0) ? 2.f * f : f;
            }
            s_pool[ln][h] = (a0 + a1) + (a2 + a3);
        }
        __syncthreads();

        // Phase B: z = relu(pool @ w1 + b1)
        #pragma unroll
        for (int q = 0; q < 4; q++) {
            const int ln = slot * 4 + q;
            float z = s_b1[h];
            #pragma unroll
            for (int f = 0; f < HID; f++) z += s_pool[ln][f] * s_w1[f * HID + h];
            s_z[ln][h] = fmaxf(z, 0.f);
        }
        __syncthreads();

        // Phase C: h2 = relu(z @ w2 + b2) + pooling contribution
        float gacc = 0.f;
        #pragma unroll
        for (int q = 0; q < 4; q++) {
            const int ln = slot * 4 + q;
            const int r = base + ln;
            float acc = s_b2[h];
            #pragma unroll
            for (int k = 0; k < HID; k++) acc += s_z[ln][k] * s_w2[k * HID + h];
            acc = fmaxf(acc, 0.f);
            g_h2[(size_t)r * HID + h] = acc;
            gacc += gp[r] * acc;
        }
        atomicAdd(&s_acc[h], gacc);
        __syncthreads();
        if (tid < HID) {
            atomicAdd(&g_gge[b * HID + tid], s_acc[tid]);
            s_acc[tid] = 0.f;
        }
    }
}

// ============================================================================
// Kernel 3: actor MLP, one warp per (batch, job); last block per batch also
// runs the masked softmax (fence + counter pattern). 256 blocks x 128 thr.
// ============================================================================
__global__ __launch_bounds__(128) void k3_actor(
    const int* __restrict__ cand, const int* __restrict__ mask,
    const float* __restrict__ pmi,
    const float* __restrict__ w1, const float* __restrict__ b1,
    const float* __restrict__ w2, const float* __restrict__ b2,
    const float* __restrict__ w3, const float* __restrict__ b3,
    float* __restrict__ out)
{
    __shared__ float s_x[4][3 * HID];
    __shared__ float s_t[4][HID];
    __shared__ float s_red[JJ];
    __shared__ int   s_ticket;

    const int w    = threadIdx.x >> 5;
    const int lane = threadIdx.x & 31;
    const int job  = blockIdx.x * 4 + w;      // 0..1023, batch uniform per block
    const int bb   = job >> 7;
    const int j    = job & 127;

    // assemble x = [job_emb | global_emb | pmi]  (192 floats)
    const int c = cand[bb * JJ + j];
    const float2* e2 = (const float2*)(g_h2 + ((size_t)bb * NN + c) * HID);
    const float2* g2 = (const float2*)(g_gge + bb * HID);
    const float2* p2 = (const float2*)pmi;
    float2 t;
    t = e2[lane]; s_x[w][2 * lane] = t.x; s_x[w][2 * lane + 1] = t.y;
    t = g2[lane]; s_x[w][HID + 2 * lane] = t.x; s_x[w][HID + 2 * lane + 1] = t.y;
    t = p2[lane]; s_x[w][2 * HID + 2 * lane] = t.x; s_x[w][2 * HID + 2 * lane + 1] = t.y;
    __syncwarp();

    // layer 1: 192 -> 64, tanh
    float a0 = b1[lane], a1 = b1[lane + 32];
    #pragma unroll 8
    for (int f = 0; f < 3 * HID; f++) {
        const float xv = s_x[w][f];
        a0 += xv * w1[f * HID + lane];
        a1 += xv * w1[f * HID + lane + 32];
    }
    s_t[w][lane] = tanhf(a0); s_t[w][lane + 32] = tanhf(a1);
    __syncwarp();

    // layer 2: 64 -> 64, tanh
    float c0 = b2[lane], c1 = b2[lane + 32];
    #pragma unroll 8
    for (int k = 0; k < HID; k++) {
        const float xv = s_t[w][k];
        c0 += xv * w2[k * HID + lane];
        c1 += xv * w2[k * HID + lane + 32];
    }

    // layer 3: 64 -> 1
    float part = tanhf(c0) * w3[lane] + tanhf(c1) * w3[lane + 32];
    #pragma unroll
    for (int o = 16; o > 0; o >>= 1)
        part += __shfl_down_sync(0xffffffffu, part, o);
    if (lane == 0) {
        float score = (part + b3[0]) * 10.0f;
        if (mask[bb * JJ + j]) score = -INFINITY;
        g_scores[job] = score;
        __threadfence();   // release this score device-wide
    }
    __syncthreads();
    if (threadIdx.x == 0)
        s_ticket = atomicAdd(&g_done[bb], 1);
    __syncthreads();

    if (s_ticket == 31) {              // last of the 32 blocks of this batch
        __threadfence();               // acquire
        const int jj = threadIdx.x;    // 128 threads = 128 jobs
        const float sc = __ldcg(&g_scores[bb * JJ + jj]);
        s_red[jj] = sc; __syncthreads();
        for (int s = JJ / 2; s > 0; s >>= 1) {
            if (jj < s) s_red[jj] = fmaxf(s_red[jj], s_red[jj + s]);
            __syncthreads();
        }
        const float mx = s_red[0]; __syncthreads();
        const float e = expf(sc - mx);
        s_red[jj] = e; __syncthreads();
        for (int s = JJ / 2; s > 0; s >>= 1) {
            if (jj < s) s_red[jj] += s_red[jj + s];
            __syncthreads();
        }
        out[bb * JJ + jj] = e / s_red[0];
    }
}

// ============================================================================
extern "C" void kernel_launch(void* const* d_in, const int* in_sizes, int n_in,
                              void* d_out, int out_size)
{
    const float* features   = (const float*)d_in[0];
    const float* graph_pool = (const float*)d_in[1];
    const float* adj        = (const float*)d_in[2];
    const int*   candidate  = (const int*)d_in[3];
    const int*   mask       = (const int*)d_in[4];
    const float* g0w1 = (const float*)d_in[5];
    const float* g0b1 = (const float*)d_in[6];
    const float* g0w2 = (const float*)d_in[7];
    const float* g0b2 = (const float*)d_in[8];
    const float* g1w1 = (const float*)d_in[9];
    const float* g1b1 = (const float*)d_in[10];
    const float* g1w2 = (const float*)d_in[11];
    const float* g1b2 = (const float*)d_in[12];
    const float* pmi  = (const float*)d_in[13];
    const float* aw1  = (const float*)d_in[14];
    const float* ab1  = (const float*)d_in[15];
    const float* aw2  = (const float*)d_in[16];
    const float* ab2  = (const float*)d_in[17];
    const float* aw3  = (const float*)d_in[18];
    const float* ab3  = (const float*)d_in[19];
    float* out = (float*)d_out;

    k1_scan<<<NROWS / 16, 512>>>(adj, features, g0w1, g0b1, g0w2, g0b2);
    k2_spmm<<<296, 256>>>(g1w1, g1b1, g1w2, g1b2, graph_pool);
    k3_actor<<<BB * JJ / 4, 128>>>(candidate, mask, pmi,
                                   aw1, ab1, aw2, ab2, aw3, ab3, out);
}